// round 1
// baseline (speedup 1.0000x reference)
#include <cuda_runtime.h>

#define BIGV 1e10f
#define TT 1024
#define BB 32
#define DD 64
#define NDIAG 2047   // row+col in [0, 2046]

// Diagonal-major cost scratch: g_cost[b][d][row], d = row+col.
// 32 * 2047 * 1024 floats = 268 MB (static __device__ scratch, sanctioned).
static __device__ float g_cost[(size_t)BB * NDIAG * TT];

// ---------------------------------------------------------------------------
// Kernel A: cost matrix, 64x64 tiles, 4x4 register tiling, K=64 fully in smem.
// Writes results in anti-diagonal-major layout so the DP kernel reads coalesced.
// ---------------------------------------------------------------------------
__global__ __launch_bounds__(256) void cost_kernel(const float* __restrict__ x,
                                                   const float* __restrict__ y) {
    const int bz = blockIdx.z;   // batch
    const int br = blockIdx.y;   // row tile (16)
    const int bc = blockIdx.x;   // col tile (16)
    const int tid = threadIdx.x; // 256 threads

    // arena holds transposed tiles during compute, then is reused as the
    // result staging buffer for the anti-diagonal write phase.
    __shared__ float arena[2 * 64 * 65];          // 33.3 KB
    __shared__ float x2s[64], y2s[64];
    float* xsT = arena;                           // xsT[k*65 + r]
    float* ysT = arena + 64 * 65;                 // ysT[k*65 + c]
    float (*res)[72] = (float (*)[72])arena;      // res[64][72] aliases arena

    const float* xb = x + ((size_t)bz * TT + br * 64) * DD;
    const float* yb = y + ((size_t)bz * TT + bc * 64) * DD;

    // Load tiles transposed: gmem coalesced (consecutive tid -> consecutive d),
    // smem stores stride-65 -> conflict-free.
    #pragma unroll
    for (int i = 0; i < 16; i++) {
        int idx = tid + i * 256;   // 0..4095
        int r = idx >> 6;
        int d = idx & 63;
        xsT[d * 65 + r] = xb[r * DD + d];
        ysT[d * 65 + r] = yb[r * DD + d];
    }
    __syncthreads();

    // Row norms (threads 0..127), then everyone does the 4x4 GEMM tile.
    if (tid < 64) {
        float s = 0.f;
        #pragma unroll
        for (int k = 0; k < 64; k++) { float v = xsT[k * 65 + tid]; s = fmaf(v, v, s); }
        x2s[tid] = s;
    } else if (tid < 128) {
        int c = tid - 64;
        float s = 0.f;
        #pragma unroll
        for (int k = 0; k < 64; k++) { float v = ysT[k * 65 + c]; s = fmaf(v, v, s); }
        y2s[c] = s;
    }

    const int tx = tid & 15;   // col group
    const int ty = tid >> 4;   // row group
    float acc[4][4] = {};
    #pragma unroll
    for (int k = 0; k < 64; k++) {
        float xr[4], yc[4];
        #pragma unroll
        for (int r = 0; r < 4; r++) xr[r] = xsT[k * 65 + ty * 4 + r];
        #pragma unroll
        for (int c = 0; c < 4; c++) yc[c] = ysT[k * 65 + tx * 4 + c];
        #pragma unroll
        for (int r = 0; r < 4; r++)
            #pragma unroll
            for (int c = 0; c < 4; c++)
                acc[r][c] = fmaf(xr[r], yc[c], acc[r][c]);
    }
    __syncthreads();  // x2s/y2s visible; all xsT/ysT reads done (safe to alias res)

    float xr2[4], yc2[4];
    #pragma unroll
    for (int r = 0; r < 4; r++) xr2[r] = x2s[ty * 4 + r];
    #pragma unroll
    for (int c = 0; c < 4; c++) yc2[c] = y2s[tx * 4 + c];
    #pragma unroll
    for (int r = 0; r < 4; r++)
        #pragma unroll
        for (int c = 0; c < 4; c++)
            res[ty * 4 + r][tx * 4 + c] =
                fmaxf(xr2[r] + yc2[c] - 2.0f * acc[r][c], 0.0f);
    __syncthreads();

    // Anti-diagonal-major writeout: warp w handles local diagonals dl = w, w+8, ...
    // Lanes write consecutive rows -> fully coalesced 128B stores.
    const int wid = tid >> 5, lane = tid & 31;
    const int dbase = br * 64 + bc * 64;
    for (int dl = wid; dl < 127; dl += 8) {
        int rlo = dl > 63 ? dl - 63 : 0;
        int rhi = dl < 63 ? dl : 63;
        size_t gbase = ((size_t)bz * NDIAG + (dbase + dl)) * TT + (size_t)br * 64;
        for (int r0 = rlo; r0 <= rhi; r0 += 32) {
            int r = r0 + lane;
            if (r <= rhi) g_cost[gbase + r] = res[r][dl - r];  // stride 71r: no conflicts
        }
    }
}

// ---------------------------------------------------------------------------
// Kernel B: anti-diagonal DP. One CTA (1024 threads) per batch.
// Thread t owns DP index idx = t+1 (row = t). 3 rotating smem buffers,
// one __syncthreads per diagonal, cost prefetched one diagonal ahead.
// ---------------------------------------------------------------------------
__global__ __launch_bounds__(1024) void dp_kernel(float* __restrict__ out) {
    const int b = blockIdx.x;
    const int t = threadIdx.x;   // 0..1023

    __shared__ float buf0[1032], buf1[1032], buf2[1032];
    float* dm2 = buf0;   // d_{k-2}
    float* dm1 = buf1;   // d_{k-1}
    float* cur = buf2;   // d_k

    dm2[t] = (t == 0) ? 0.0f : BIGV;
    dm1[t] = BIGV;
    if (t == 0) { dm2[1024] = BIGV; dm1[1024] = BIGV; }
    __syncthreads();

    // diag k valid for this thread iff 0 <= (k - t - 2) <= T-1
    const int kmin = t + 2;
    const int kmax = t + 2 + TT - 1;
    const float* costcol = g_cost + (size_t)b * NDIAG * TT + t;

    float pref = (t == 0) ? __ldg(costcol) : 0.0f;   // cost for k=2 (d=0)
    float result = BIGV;

    for (int k = 2; k <= 2 * TT; k++) {
        float cost = pref;
        // prefetch next diagonal's cost while we compute this one
        int kn = k + 1;
        if (kn <= 2 * TT) {
            bool v = (kn >= kmin) & (kn <= kmax);
            pref = v ? __ldg(costcol + (size_t)(kn - 2) * TT) : 0.0f;
        }

        float a  = dm2[t];       // d_{k-2}[idx-1]   (diagonal move)
        float bb = dm1[t];       // d_{k-1}[idx-1]
        float c  = dm1[t + 1];   // d_{k-1}[idx]
        float mn = fminf(a, fminf(bb, c));
        float s  = __expf(mn - a) + __expf(mn - bb) + __expf(mn - c);
        float sm = mn - __logf(s);   // gamma = 1

        float val = ((k >= kmin) & (k <= kmax)) ? (cost + sm) : BIGV;
        cur[t + 1] = val;
        if (t == 0) cur[0] = BIGV;
        __syncthreads();

        float* tmp = dm2; dm2 = dm1; dm1 = cur; cur = tmp;
        result = val;
    }

    // answer = d_{2T}[T], computed by thread t = T-1 on the last diagonal
    if (t == TT - 1) out[b] = result;
}

extern "C" void kernel_launch(void* const* d_in, const int* in_sizes, int n_in,
                              void* d_out, int out_size) {
    const float* x = (const float*)d_in[0];
    const float* y = (const float*)d_in[1];
    float* out = (float*)d_out;

    dim3 gridA(TT / 64, TT / 64, BB);   // (16, 16, 32)
    cost_kernel<<<gridA, 256>>>(x, y);
    dp_kernel<<<BB, 1024>>>(out);
}